// round 4
// baseline (speedup 1.0000x reference)
#include <cuda_runtime.h>

#define BATCH  256
#define PART   128
#define ONODES 64
#define INODES 64
#define BT     64
#define NT     256

// Precomputed softmax(weight), transposed: [p][i][o]
__device__ float g_sw[PART * INODES * ONODES];

__device__ __forceinline__ void ffma2(unsigned long long& d,
                                      unsigned long long a,
                                      unsigned long long b) {
    asm("fma.rn.f32x2 %0, %1, %2, %0;" : "+l"(d) : "l"(a), "l"(b));
}
__device__ __forceinline__ float2 unpack2(unsigned long long a) {
    float2 r;
    r.x = __uint_as_float((unsigned)(a & 0xffffffffu));
    r.y = __uint_as_float((unsigned)(a >> 32));
    return r;
}

// ---- Kernel A: softmax(weight[p][o][:]) -> g_sw[p][i][o] (transposed) -----
// One CTA per p, 256 threads. Softmax in registers, transpose via padded smem,
// coalesced float4 stores.
__global__ __launch_bounds__(256)
void softmaxw_kernel(const float* __restrict__ weight) {
    __shared__ float sWs[INODES][ONODES + 4];   // pad 4: keeps rows 16B-aligned

    const int p   = blockIdx.x;
    const int tid = threadIdx.x;

    // softmax: 4 lanes per o-row, 16 i's each
    {
        const int o = tid >> 2;
        const int j = tid & 3;
        const float4* wrow = reinterpret_cast<const float4*>(
            weight + ((size_t)p * ONODES + o) * INODES + j * 16);
        float v[16];
        #pragma unroll
        for (int q = 0; q < 4; q++) {
            float4 t = wrow[q];
            v[4*q+0] = t.x; v[4*q+1] = t.y; v[4*q+2] = t.z; v[4*q+3] = t.w;
        }
        float m = v[0];
        #pragma unroll
        for (int q = 1; q < 16; q++) m = fmaxf(m, v[q]);
        m = fmaxf(m, __shfl_xor_sync(0xffffffffu, m, 1));
        m = fmaxf(m, __shfl_xor_sync(0xffffffffu, m, 2));
        float s = 0.0f;
        #pragma unroll
        for (int q = 0; q < 16; q++) { v[q] = __expf(v[q] - m); s += v[q]; }
        s += __shfl_xor_sync(0xffffffffu, s, 1);
        s += __shfl_xor_sync(0xffffffffu, s, 2);
        float inv = __fdividef(1.0f, s);
        #pragma unroll
        for (int q = 0; q < 16; q++) sWs[j * 16 + q][o] = v[q] * inv;
    }
    __syncthreads();

    // coalesced write-out: thread -> float4 at [i][o0..o0+3]
    float* dst = g_sw + (size_t)p * INODES * ONODES;
    #pragma unroll
    for (int q = 0; q < 4; q++) {
        int f  = tid + q * 256;              // 0..1023
        int i  = f >> 4;
        int o0 = (f & 15) * 4;
        float4 t;
        t.x = sWs[i][o0 + 0];
        t.y = sWs[i][o0 + 1];
        t.z = sWs[i][o0 + 2];
        t.w = sWs[i][o0 + 3];
        *reinterpret_cast<float4*>(dst + i * ONODES + o0) = t;
    }
}

// ---- Kernel B: main -------------------------------------------------------
// out[b,p,o] = log( sum_i exp(x[b,p,i]) * softmaxW[p,o,i] )
// (no max shift: x ~ N(0,1), exp(x) well inside fp32 range; tol 1e-3)
__global__ __launch_bounds__(NT, 4)
void sumlayer_kernel(const float* __restrict__ x,
                     float* __restrict__ out) {
    __shared__ float2 sXT[INODES * BT];      // [i][r] = {e,e}   32 KB
    __shared__ float  sW[INODES][ONODES];    // [i][o]           16 KB

    const int p   = blockIdx.y;
    const int b0  = blockIdx.x * BT;
    const int tid = threadIdx.x;

    // -- load softmax(weight)[p]: already [i][o], pure coalesced copy --------
    {
        const float4* src = reinterpret_cast<const float4*>(
            g_sw + (size_t)p * INODES * ONODES);
        float4* dst = reinterpret_cast<float4*>(&sW[0][0]);
        #pragma unroll
        for (int q = 0; q < 4; q++)
            dst[tid + q * NT] = src[tid + q * NT];
    }

    // -- phase X: exp(x) -> duplicated pairs, transposed sXT[i][r] ----------
    // warp = 32 consecutive r, same j  =>  STS.64 stride-8B, conflict-free
    {
        const int r = tid & 63;
        const int j = tid >> 6;              // i-quarter
        const float4* xrow = reinterpret_cast<const float4*>(
            x + ((size_t)(b0 + r) * PART + p) * INODES + j * 16);
        #pragma unroll
        for (int q = 0; q < 4; q++) {
            float4 t = xrow[q];
            int i0 = j * 16 + q * 4;
            float e0 = __expf(t.x), e1 = __expf(t.y);
            float e2 = __expf(t.z), e3 = __expf(t.w);
            sXT[(i0 + 0) * BT + r] = make_float2(e0, e0);
            sXT[(i0 + 1) * BT + r] = make_float2(e1, e1);
            sXT[(i0 + 2) * BT + r] = make_float2(e2, e2);
            sXT[(i0 + 3) * BT + r] = make_float2(e3, e3);
        }
    }
    __syncthreads();

    // -- GEMM: acc[r][o] = sum_i e[r][i] * w[i][o]   (f32x2, o-paired) ------
    const int tx = tid & 15;
    const int ty = tid >> 4;
    const int o0 = tx * 4;
    const int r0 = ty * 4;

    unsigned long long a00 = 0, a01 = 0, a10 = 0, a11 = 0;
    unsigned long long a20 = 0, a21 = 0, a30 = 0, a31 = 0;

    const float2* xp = sXT + r0;

    #pragma unroll
    for (int i = 0; i < INODES; i += 2) {
        ulonglong2 xa0 = *reinterpret_cast<const ulonglong2*>(xp + i * BT);
        ulonglong2 xa1 = *reinterpret_cast<const ulonglong2*>(xp + i * BT + 2);
        ulonglong2 xb0 = *reinterpret_cast<const ulonglong2*>(xp + (i + 1) * BT);
        ulonglong2 xb1 = *reinterpret_cast<const ulonglong2*>(xp + (i + 1) * BT + 2);
        ulonglong2 wa = *reinterpret_cast<const ulonglong2*>(&sW[i][o0]);
        ulonglong2 wb = *reinterpret_cast<const ulonglong2*>(&sW[i + 1][o0]);

        ffma2(a00, xa0.x, wa.x); ffma2(a01, xa0.x, wa.y);
        ffma2(a10, xa0.y, wa.x); ffma2(a11, xa0.y, wa.y);
        ffma2(a20, xa1.x, wa.x); ffma2(a21, xa1.x, wa.y);
        ffma2(a30, xa1.y, wa.x); ffma2(a31, xa1.y, wa.y);

        ffma2(a00, xb0.x, wb.x); ffma2(a01, xb0.x, wb.y);
        ffma2(a10, xb0.y, wb.x); ffma2(a11, xb0.y, wb.y);
        ffma2(a20, xb1.x, wb.x); ffma2(a21, xb1.x, wb.y);
        ffma2(a30, xb1.y, wb.x); ffma2(a31, xb1.y, wb.y);
    }

    // -- epilogue: out = log(acc) ------------------------------------------
    unsigned long long accs[4][2] = {{a00, a01}, {a10, a11},
                                     {a20, a21}, {a30, a31}};
    #pragma unroll
    for (int j = 0; j < 4; j++) {
        float2 lo = unpack2(accs[j][0]);
        float2 hi = unpack2(accs[j][1]);
        float4 o4;
        o4.x = __logf(lo.x);
        o4.y = __logf(lo.y);
        o4.z = __logf(hi.x);
        o4.w = __logf(hi.y);
        *reinterpret_cast<float4*>(
            &out[((size_t)(b0 + r0 + j) * PART + p) * ONODES + o0]) = o4;
    }
}

extern "C" void kernel_launch(void* const* d_in, const int* in_sizes, int n_in,
                              void* d_out, int out_size) {
    const float* x      = (const float*)d_in[0];   // [256,128,64]
    const float* weight = (const float*)d_in[1];   // [128,64,64]
    float* out          = (float*)d_out;           // [256,128,64]

    softmaxw_kernel<<<PART, 256>>>(weight);
    sumlayer_kernel<<<dim3(BATCH / BT, PART), NT>>>(x, out);
}

// round 5
// speedup vs baseline: 1.5209x; 1.5209x over previous
#include <cuda_runtime.h>

#define BATCH  256
#define PART   128
#define ONODES 64
#define INODES 64
#define BT     64
#define NT     256

__device__ __forceinline__ void ffma2(unsigned long long& d,
                                      unsigned long long a,
                                      unsigned long long b) {
    asm("fma.rn.f32x2 %0, %1, %2, %0;" : "+l"(d) : "l"(a), "l"(b));
}
__device__ __forceinline__ float2 unpack2(unsigned long long a) {
    float2 r;
    r.x = __uint_as_float((unsigned)(a & 0xffffffffu));
    r.y = __uint_as_float((unsigned)(a >> 32));
    return r;
}

// Single fused kernel.
// out[b,p,o] = log( sum_i exp(x[b,p,i]) * softmax_i(weight[p,o,:]) )
// (no max shift on x: x ~ N(0,1), exp(x) comfortably inside fp32; tol 1e-3.
//  softmax on weight keeps its own max shift for exactness.)
__global__ __launch_bounds__(NT)
void sumlayer_kernel(const float* __restrict__ x,
                     const float* __restrict__ weight,
                     float* __restrict__ out) {
    __shared__ float2 sXT[INODES * BT];      // [i][r] = {e,e}   32 KB
    __shared__ float  sW[INODES][ONODES];    // softmaxW [i][o]  16 KB

    const int p   = blockIdx.y;
    const int b0  = blockIdx.x * BT;
    const int tid = threadIdx.x;

    // -- phase W: softmax(weight[p][o][:]) -> sW[i][o] ----------------------
    // 4 lanes per o-row, 16 i's each; warp reads 2KB contiguous (coalesced).
    {
        const int o = tid >> 2;
        const int j = tid & 3;
        const float4* wrow = reinterpret_cast<const float4*>(
            weight + ((size_t)p * ONODES + o) * INODES + j * 16);
        float v[16];
        #pragma unroll
        for (int q = 0; q < 4; q++) {
            float4 t = wrow[q];
            v[4*q+0] = t.x; v[4*q+1] = t.y; v[4*q+2] = t.z; v[4*q+3] = t.w;
        }
        float m = v[0];
        #pragma unroll
        for (int q = 1; q < 16; q++) m = fmaxf(m, v[q]);
        m = fmaxf(m, __shfl_xor_sync(0xffffffffu, m, 1));
        m = fmaxf(m, __shfl_xor_sync(0xffffffffu, m, 2));
        float s = 0.0f;
        #pragma unroll
        for (int q = 0; q < 16; q++) { v[q] = __expf(v[q] - m); s += v[q]; }
        s += __shfl_xor_sync(0xffffffffu, s, 1);
        s += __shfl_xor_sync(0xffffffffu, s, 2);
        float inv = __fdividef(1.0f, s);
        #pragma unroll
        for (int q = 0; q < 16; q++)
            sW[j * 16 + q][o] = v[q] * inv;          // 4-way conflict, cheap
    }

    // -- phase X: exp(x) -> duplicated pairs, transposed sXT[i][r] ----------
    // warp = 32 consecutive r, same j  =>  STS.64 stride-8B, conflict-free
    {
        const int r = tid & 63;
        const int j = tid >> 6;              // i-quarter
        const float4* xrow = reinterpret_cast<const float4*>(
            x + ((size_t)(b0 + r) * PART + p) * INODES + j * 16);
        #pragma unroll
        for (int q = 0; q < 4; q++) {
            float4 t = xrow[q];
            int i0 = j * 16 + q * 4;
            float e0 = __expf(t.x), e1 = __expf(t.y);
            float e2 = __expf(t.z), e3 = __expf(t.w);
            sXT[(i0 + 0) * BT + r] = make_float2(e0, e0);
            sXT[(i0 + 1) * BT + r] = make_float2(e1, e1);
            sXT[(i0 + 2) * BT + r] = make_float2(e2, e2);
            sXT[(i0 + 3) * BT + r] = make_float2(e3, e3);
        }
    }
    __syncthreads();

    // -- GEMM: acc[r][o] = sum_i e[r][i] * w[i][o]   (f32x2, o-paired) ------
    const int tx = tid & 15;
    const int ty = tid >> 4;
    const int o0 = tx * 4;
    const int r0 = ty * 4;

    unsigned long long a00 = 0, a01 = 0, a10 = 0, a11 = 0;
    unsigned long long a20 = 0, a21 = 0, a30 = 0, a31 = 0;

    const float2* xp = sXT + r0;

    #pragma unroll
    for (int i = 0; i < INODES; i += 2) {
        ulonglong2 xa0 = *reinterpret_cast<const ulonglong2*>(xp + i * BT);
        ulonglong2 xa1 = *reinterpret_cast<const ulonglong2*>(xp + i * BT + 2);
        ulonglong2 xb0 = *reinterpret_cast<const ulonglong2*>(xp + (i + 1) * BT);
        ulonglong2 xb1 = *reinterpret_cast<const ulonglong2*>(xp + (i + 1) * BT + 2);
        ulonglong2 wa = *reinterpret_cast<const ulonglong2*>(&sW[i][o0]);
        ulonglong2 wb = *reinterpret_cast<const ulonglong2*>(&sW[i + 1][o0]);

        ffma2(a00, xa0.x, wa.x); ffma2(a01, xa0.x, wa.y);
        ffma2(a10, xa0.y, wa.x); ffma2(a11, xa0.y, wa.y);
        ffma2(a20, xa1.x, wa.x); ffma2(a21, xa1.x, wa.y);
        ffma2(a30, xa1.y, wa.x); ffma2(a31, xa1.y, wa.y);

        ffma2(a00, xb0.x, wb.x); ffma2(a01, xb0.x, wb.y);
        ffma2(a10, xb0.y, wb.x); ffma2(a11, xb0.y, wb.y);
        ffma2(a20, xb1.x, wb.x); ffma2(a21, xb1.x, wb.y);
        ffma2(a30, xb1.y, wb.x); ffma2(a31, xb1.y, wb.y);
    }

    // -- epilogue: out = log(acc) ------------------------------------------
    unsigned long long accs[4][2] = {{a00, a01}, {a10, a11},
                                     {a20, a21}, {a30, a31}};
    #pragma unroll
    for (int j = 0; j < 4; j++) {
        float2 lo = unpack2(accs[j][0]);
        float2 hi = unpack2(accs[j][1]);
        float4 o4;
        o4.x = __logf(lo.x);
        o4.y = __logf(lo.y);
        o4.z = __logf(hi.x);
        o4.w = __logf(hi.y);
        *reinterpret_cast<float4*>(
            &out[((size_t)(b0 + r0 + j) * PART + p) * ONODES + o0]) = o4;
    }
}

extern "C" void kernel_launch(void* const* d_in, const int* in_sizes, int n_in,
                              void* d_out, int out_size) {
    const float* x      = (const float*)d_in[0];   // [256,128,64]
    const float* weight = (const float*)d_in[1];   // [128,64,64]
    float* out          = (float*)d_out;           // [256,128,64]

    sumlayer_kernel<<<dim3(BATCH / BT, PART), NT>>>(x, weight, out);
}